// round 10
// baseline (speedup 1.0000x reference)
#include <cuda_runtime.h>
#include <stdint.h>

#define BATCH   512
#define EMB     512
#define NCLS    100

#define KSPLIT  4
#define KSLICE  (EMB / KSPLIT)   // 128
#define BM      64
#define BN      128
#define BK      32
#define MAXPOS  64
#define LDPAD   40               // smem row stride (words): conflict-free LDS.64

__device__ float    g_D[KSPLIT][BATCH * BATCH];
__device__ float    g_Xr[BATCH * EMB];   // tf32(RNA)-rounded X, k-permuted per 8-group
__device__ unsigned g_cnt;               // monotonic grid-sync counter

#define CP_ASYNC16(dst_u32, src_ptr) \
    asm volatile("cp.async.ca.shared.global [%0], [%1], 16;" \
                 :: "r"(dst_u32), "l"(src_ptr))
#define CP_COMMIT() asm volatile("cp.async.commit_group;")
#define CP_WAIT(n)  asm volatile("cp.async.wait_group %0;" :: "n"(n))

__device__ __forceinline__ uint32_t smem_u32(const void* p) {
    return (uint32_t)__cvta_generic_to_shared(p);
}
__device__ __forceinline__ float f2tf32f(float f) {
    uint32_t r;
    asm("cvt.rna.tf32.f32 %0, %1;" : "=r"(r) : "f"(f));
    return __uint_as_float(r);
}

// ---------------------------------------------------------------------------
// Kernel 1: prologue rounds X -> g_Xr (tf32 RNA) with in-8-group k-permutation
// (k = t + 4h stored at p = 2t + h), grid sync, then tf32 MMA GEMM with
// cp.async double-buffered pipeline and LDS.64 fragment loads.
// ---------------------------------------------------------------------------
__global__ __launch_bounds__(256) void gemm_xxT_tc(const float* __restrict__ X,
                                                   const float* __restrict__ mu,
                                                   const float* __restrict__ nv,
                                                   float* __restrict__ out) {
    __shared__ uint32_t As[2][BM][LDPAD];
    __shared__ uint32_t Bs[2][BN][LDPAD];

    const int tid = threadIdx.x;
    const int bx = blockIdx.x;          // N tile (0..3)
    const int by = blockIdx.y;          // M tile (0..7)
    const int bz = blockIdx.z;          // K slice (0..3)
    const int k0 = bz * KSLICE;
    const int cta = bx + 4 * (by + 8 * bz);   // 0..127

    // ---- Phase 0: round + permute X once (one 8-group per thread) ----
    {
        const int base = (cta * 256 + tid) * 8;
        float4 lo = *(const float4*)&X[base];
        float4 hi = *(const float4*)&X[base + 4];
        float4 o0 = make_float4(f2tf32f(lo.x), f2tf32f(hi.x),
                                f2tf32f(lo.y), f2tf32f(hi.y));
        float4 o1 = make_float4(f2tf32f(lo.z), f2tf32f(hi.z),
                                f2tf32f(lo.w), f2tf32f(hi.w));
        *(float4*)&g_Xr[base]     = o0;
        *(float4*)&g_Xr[base + 4] = o1;
    }

    if (cta == 0 && tid == 0) {
        float s = 0.f;
        for (int c = 0; c < NCLS; c++) s += mu[c] + nv[c];
        out[0] = -s * (1.0f / NCLS);
    }

    // ---- Grid sync (monotonic counter, replay-safe; 128 CTAs = 1 wave) ----
    __threadfence();
    __syncthreads();
    if (tid == 0) {
        unsigned t = atomicAdd(&g_cnt, 1u);
        unsigned target = ((t >> 7) + 1u) << 7;     // next multiple of 128
        while (*(volatile unsigned*)&g_cnt < target) { }
        __threadfence();
    }
    __syncthreads();

    // ---- Phase 1: GEMM ----
    const int w    = tid >> 5;
    const int lane = tid & 31;
    const int g    = lane >> 2;
    const int tig  = lane & 3;
    const int wm   = w & 1;
    const int wn   = w >> 1;

    auto issue_tile = [&](int kt, int buf) {
        #pragma unroll
        for (int l = 0; l < 2; l++) {
            int idx = tid + l * 256;
            int r = idx >> 3, c = (idx & 7) * 4;
            CP_ASYNC16(smem_u32(&As[buf][r][c]),
                       &g_Xr[(by * BM + r) * EMB + k0 + kt + c]);
        }
        #pragma unroll
        for (int l = 0; l < 4; l++) {
            int idx = tid + l * 256;
            int r = idx >> 3, c = (idx & 7) * 4;
            CP_ASYNC16(smem_u32(&Bs[buf][r][c]),
                       &g_Xr[(bx * BN + r) * EMB + k0 + kt + c]);
        }
        CP_COMMIT();
    };

    float acc[2][4][4] = {};

    issue_tile(0, 0);

    #pragma unroll
    for (int kt4 = 0; kt4 < 4; kt4++) {
        const int cur = kt4 & 1;
        __syncthreads();
        if (kt4 < 3) issue_tile((kt4 + 1) * BK, cur ^ 1);
        if (kt4 < 3) { CP_WAIT(1); } else { CP_WAIT(0); }
        __syncthreads();

        #pragma unroll
        for (int kk = 0; kk < BK; kk += 8) {
            // permuted layout: physical (kk + 2*tig, +1) = logical k (tig, tig+4)
            uint2 a_lo[2], a_hi[2], bv[4];
            #pragma unroll
            for (int mi = 0; mi < 2; mi++) {
                int r0 = wm * 32 + mi * 16;
                a_lo[mi] = *(const uint2*)&As[cur][r0 + g    ][kk + 2 * tig];
                a_hi[mi] = *(const uint2*)&As[cur][r0 + g + 8][kk + 2 * tig];
            }
            #pragma unroll
            for (int ni = 0; ni < 4; ni++) {
                int n0 = wn * 32 + ni * 8;
                bv[ni] = *(const uint2*)&Bs[cur][n0 + g][kk + 2 * tig];
            }
            #pragma unroll
            for (int mi = 0; mi < 2; mi++)
                #pragma unroll
                for (int ni = 0; ni < 4; ni++) {
                    asm volatile(
                        "mma.sync.aligned.m16n8k8.row.col.f32.tf32.tf32.f32 "
                        "{%0,%1,%2,%3}, {%4,%5,%6,%7}, {%8,%9}, {%0,%1,%2,%3};"
                        : "+f"(acc[mi][ni][0]), "+f"(acc[mi][ni][1]),
                          "+f"(acc[mi][ni][2]), "+f"(acc[mi][ni][3])
                        : "r"(a_lo[mi].x), "r"(a_hi[mi].x),
                          "r"(a_lo[mi].y), "r"(a_hi[mi].y),
                          "r"(bv[ni].x),   "r"(bv[ni].y));
                }
        }
    }

    float* Dz = g_D[bz];
    #pragma unroll
    for (int mi = 0; mi < 2; mi++) {
        #pragma unroll
        for (int ni = 0; ni < 4; ni++) {
            int r = by * BM + wm * 32 + mi * 16 + g;
            int c = bx * BN + wn * 32 + ni * 8 + 2 * tig;
            *(float2*)&Dz[r * BATCH + c]       = make_float2(acc[mi][ni][0], acc[mi][ni][1]);
            *(float2*)&Dz[(r + 8) * BATCH + c] = make_float2(acc[mi][ni][2], acc[mi][ni][3]);
        }
    }
}

// ---------------------------------------------------------------------------
// Kernel 2: block-per-anchor hinge (512 CTAs). No labels smem array; mu[li]
// prefetched via direct LDG chain at top (off the barrier-ordered path).
// ---------------------------------------------------------------------------
__global__ __launch_bounds__(256) void row_loss(const int* __restrict__ labels,
                                                const float* __restrict__ mu,
                                                float* __restrict__ out) {
    const int i    = blockIdx.x;
    const int tid  = threadIdx.x;
    const int w    = tid >> 5;
    const int lane = tid & 31;

    __shared__ float posv[MAXPOS];
    __shared__ int   npos;
    __shared__ float red[8];

    const int c0 = 2 * tid;

    // independent load chains, all issued up front
    const int   li  = __ldg(&labels[i]);
    const int2  lb  = *(const int2*)&labels[c0];
    float2 rv = make_float2(0.f, 0.f);
    #pragma unroll
    for (int z = 0; z < KSPLIT; z++) {
        float2 v = __ldcg((const float2*)&g_D[z][i * BATCH + c0]);
        rv.x += v.x; rv.y += v.y;
    }
    const float mui = __ldg(&mu[li]);

    if (tid == 0) npos = 0;
    __syncthreads();

    bool p0 = (c0     != i) && (lb.x == li);
    bool p1 = (c0 + 1 != i) && (lb.y == li);
    if (p0) { int s = atomicAdd(&npos, 1); if (s < MAXPOS) posv[s] = rv.x; }
    if (p1) { int s = atomicAdd(&npos, 1); if (s < MAXPOS) posv[s] = rv.y; }
    __syncthreads();

    int np = npos; if (np > MAXPOS) np = MAXPOS;

    float s = 0.f;
    if (lb.x != li) {
        float b = mui - rv.x;
        for (int p = 0; p < np; p++) s += fmaxf(posv[p] + b, 0.f);
    }
    if (lb.y != li) {
        float b = mui - rv.y;
        for (int p = 0; p < np; p++) s += fmaxf(posv[p] + b, 0.f);
    }

    #pragma unroll
    for (int o = 16; o > 0; o >>= 1) s += __shfl_xor_sync(0xffffffffu, s, o);
    if (lane == 0) red[w] = s;
    __syncthreads();
    if (w == 0) {
        float v = (lane < 8) ? red[lane] : 0.f;
        #pragma unroll
        for (int o = 4; o > 0; o >>= 1) v += __shfl_xor_sync(0xffffffffu, v, o);
        if (lane == 0) atomicAdd(out, v);
    }
}

// ---------------------------------------------------------------------------
extern "C" void kernel_launch(void* const* d_in, const int* in_sizes, int n_in,
                              void* d_out, int out_size) {
    const float* X      = (const float*)d_in[0];
    const int*   labels = (const int*)d_in[1];
    const float* mu     = (const float*)d_in[2];
    const float* nv     = (const float*)d_in[3];
    float*       out    = (float*)d_out;

    dim3 ggrid(BATCH / BN, BATCH / BM, KSPLIT);   // 4 x 8 x 4 = 128 CTAs
    gemm_xxT_tc<<<ggrid, 256>>>(X, mu, nv, out);
    row_loss<<<BATCH, 256>>>(labels, mu, out);
}